// round 2
// baseline (speedup 1.0000x reference)
#include <cuda_runtime.h>

#define D   256
#define KC  1024
#define BM  128
#define BN  128
#define BK  16
#define XS_STRIDE (BM + 4)

typedef unsigned long long ull;

__device__ double g_loss_accum;
__device__ __align__(16) float g_enorm[KC];

__device__ __forceinline__ ull pack2(float lo, float hi) {
    ull r; asm("mov.b64 %0, {%1, %2};" : "=l"(r) : "f"(lo), "f"(hi)); return r;
}
__device__ __forceinline__ void unpack2(ull v, float &lo, float &hi) {
    asm("mov.b64 {%0, %1}, %2;" : "=f"(lo), "=f"(hi) : "l"(v));
}
__device__ __forceinline__ void ffma2(ull &d, ull a, ull b) {
    asm("fma.rn.f32x2 %0, %1, %2, %0;" : "+l"(d) : "l"(a), "l"(b));
}

// ---------------------------------------------------------------------------
// Prep: per-code ||e||^2 and zero the loss accumulator (every launch).
// ---------------------------------------------------------------------------
__global__ void vq_prep(const float* __restrict__ E) {
    int code = blockIdx.x;
    int t = threadIdx.x;  // 64 threads
    const float4* row = (const float4*)(E + (size_t)code * D);
    float4 v = row[t];
    float s = v.x * v.x + v.y * v.y + v.z * v.z + v.w * v.w;
    #pragma unroll
    for (int o = 16; o > 0; o >>= 1) s += __shfl_xor_sync(0xFFFFFFFFu, s, o);
    __shared__ float ws[2];
    if ((t & 31) == 0) ws[t >> 5] = s;
    __syncthreads();
    if (t == 0) {
        g_enorm[code] = ws[0] + ws[1];
        if (code == 0) g_loss_accum = 0.0;
    }
}

// ---------------------------------------------------------------------------
// Main: fused GEMM + fp32-grid argmin (reference-faithful) + STE gather + loss.
// Grid: M/BM blocks of 256 threads (16 tx x 16 ty), 8x8 microtile.
// ---------------------------------------------------------------------------
__global__ void __launch_bounds__(256, 2)
vq_main(const float* __restrict__ X, const float* __restrict__ E,
        float* __restrict__ out) {
    __shared__ float Xs[BK][XS_STRIDE];
    __shared__ float Es[BK][XS_STRIDE];
    __shared__ float s_xnorm[BM];
    __shared__ int   s_bidx[BM];
    __shared__ float s_red[8];

    const int tid  = threadIdx.x;
    const int tx   = tid & 15;
    const int ty   = tid >> 4;
    const int row0 = blockIdx.x * BM;

    const int lm  = tid >> 2;        // 0..63 (second slot at lm+64)
    const int lk4 = (tid & 3) * 4;   // 0,4,8,12

    // ---- per-row ||x||^2 (any fp32 value is fine; comparisons are invariant
    //      to exact-multiple-of-ulp shifts thanks to monotone uniform rounding)
    {
        int r = tid >> 1;            // 0..127
        int h = tid & 1;             // half of the row
        const float4* xr = (const float4*)(X + (size_t)(row0 + r) * D + h * 128);
        float s = 0.f;
        #pragma unroll
        for (int j = 0; j < 32; j++) {
            float4 v = xr[j];
            s += v.x * v.x + v.y * v.y + v.z * v.z + v.w * v.w;
        }
        s += __shfl_xor_sync(0xFFFFFFFFu, s, 1);
        if (h == 0) s_xnorm[r] = s;
    }
    __syncthreads();

    float Xn[8];
    #pragma unroll
    for (int i = 0; i < 8; i++) Xn[i] = s_xnorm[ty * 8 + i];

    float bestv[8];
    int   bestn[8];
    #pragma unroll
    for (int i = 0; i < 8; i++) { bestv[i] = 3.0e38f; bestn[i] = 0; }

    for (int nc = 0; nc < KC; nc += BN) {
        ull acc[8][4];
        #pragma unroll
        for (int i = 0; i < 8; i++)
            #pragma unroll
            for (int j = 0; j < 4; j++) acc[i][j] = 0ull;

        for (int k0 = 0; k0 < D; k0 += BK) {
            float4 xv0 = *(const float4*)(X + (size_t)(row0 + lm)      * D + k0 + lk4);
            float4 xv1 = *(const float4*)(X + (size_t)(row0 + lm + 64) * D + k0 + lk4);
            float4 ev0 = *(const float4*)(E + (size_t)(nc + lm)        * D + k0 + lk4);
            float4 ev1 = *(const float4*)(E + (size_t)(nc + lm + 64)   * D + k0 + lk4);
            __syncthreads();   // previous compute done reading smem
            Xs[lk4 + 0][lm] = xv0.x; Xs[lk4 + 1][lm] = xv0.y;
            Xs[lk4 + 2][lm] = xv0.z; Xs[lk4 + 3][lm] = xv0.w;
            Xs[lk4 + 0][lm + 64] = xv1.x; Xs[lk4 + 1][lm + 64] = xv1.y;
            Xs[lk4 + 2][lm + 64] = xv1.z; Xs[lk4 + 3][lm + 64] = xv1.w;
            Es[lk4 + 0][lm] = ev0.x; Es[lk4 + 1][lm] = ev0.y;
            Es[lk4 + 2][lm] = ev0.z; Es[lk4 + 3][lm] = ev0.w;
            Es[lk4 + 0][lm + 64] = ev1.x; Es[lk4 + 1][lm + 64] = ev1.y;
            Es[lk4 + 2][lm + 64] = ev1.z; Es[lk4 + 3][lm + 64] = ev1.w;
            __syncthreads();   // tiles ready

            #pragma unroll
            for (int k = 0; k < BK; k++) {
                float4 xa = *(const float4*)&Xs[k][ty * 8];
                float4 xb = *(const float4*)&Xs[k][ty * 8 + 4];
                float4 ea = *(const float4*)&Es[k][tx * 8];
                float4 eb = *(const float4*)&Es[k][tx * 8 + 4];
                ull ep0 = pack2(ea.x, ea.y), ep1 = pack2(ea.z, ea.w);
                ull ep2 = pack2(eb.x, eb.y), ep3 = pack2(eb.z, eb.w);
                float xv[8] = {xa.x, xa.y, xa.z, xa.w, xb.x, xb.y, xb.z, xb.w};
                #pragma unroll
                for (int i = 0; i < 8; i++) {
                    ull xp = pack2(xv[i], xv[i]);
                    ffma2(acc[i][0], xp, ep0);
                    ffma2(acc[i][1], xp, ep1);
                    ffma2(acc[i][2], xp, ep2);
                    ffma2(acc[i][3], xp, ep3);
                }
            }
        }

        // -------- epilogue: reference-faithful fp32 grid --------
        // d = fl32( fl32(xnorm + enorm_j) - fl32(2*dot_j) );  2*dot exact in fp32,
        // so fmaf(-2, dot, t) reproduces the reference's two-step rounding.
        float4 en0 = *(const float4*)&g_enorm[nc + tx * 8];
        float4 en1 = *(const float4*)&g_enorm[nc + tx * 8 + 4];
        float en[8] = {en0.x, en0.y, en0.z, en0.w, en1.x, en1.y, en1.z, en1.w};

        #pragma unroll
        for (int i = 0; i < 8; i++) {
            float bv = 3.0e38f; int bn = 0;
            #pragma unroll
            for (int j2 = 0; j2 < 4; j2++) {
                float d0, d1; unpack2(acc[i][j2], d0, d1);
                float t0 = __fadd_rn(Xn[i], en[j2 * 2]);
                float t1 = __fadd_rn(Xn[i], en[j2 * 2 + 1]);
                float s0 = __fmaf_rn(-2.f, d0, t0);
                float s1 = __fmaf_rn(-2.f, d1, t1);
                int n0 = nc + tx * 8 + j2 * 2;
                if (s0 < bv) { bv = s0; bn = n0; }
                if (s1 < bv) { bv = s1; bn = n0 + 1; }
            }
            // butterfly over the 16 tx lanes (same ty = same rows), lowest-index ties
            #pragma unroll
            for (int o = 1; o < 16; o <<= 1) {
                float ov = __shfl_xor_sync(0xFFFFFFFFu, bv, o);
                int   on = __shfl_xor_sync(0xFFFFFFFFu, bn, o);
                if (ov < bv || (ov == bv && on < bn)) { bv = ov; bn = on; }
            }
            if (bv < bestv[i] || (bv == bestv[i] && bn < bestn[i])) {
                bestv[i] = bv; bestn[i] = bn;
            }
        }
    }

    // -------- write best indices; accumulate loss partial --------
    float lsum = 0.f;
    if (tx == 0) {
        #pragma unroll
        for (int i = 0; i < 8; i++) { s_bidx[ty * 8 + i] = bestn[i]; lsum += bestv[i]; }
    }
    #pragma unroll
    for (int o = 16; o > 0; o >>= 1) lsum += __shfl_xor_sync(0xFFFFFFFFu, lsum, o);
    if ((tid & 31) == 0) s_red[tid >> 5] = lsum;
    __syncthreads();
    if (tid == 0) {
        float t = 0.f;
        #pragma unroll
        for (int w = 0; w < 8; w++) t += s_red[w];
        atomicAdd(&g_loss_accum, (double)t);
    }

    // -------- STE output: out = fl(x + fl(q - x)) (bit-exact vs reference) ----
    for (int u = tid; u < BM * (D / 4); u += 256) {
        int m = u >> 6;     // D/4 = 64 float4 per row
        int c = u & 63;
        int code = s_bidx[m];
        float4 q = *(const float4*)(E + (size_t)code * D + c * 4);
        float4 x = *(const float4*)(X + (size_t)(row0 + m) * D + c * 4);
        float4 r;
        r.x = __fadd_rn(x.x, __fsub_rn(q.x, x.x));
        r.y = __fadd_rn(x.y, __fsub_rn(q.y, x.y));
        r.z = __fadd_rn(x.z, __fsub_rn(q.z, x.z));
        r.w = __fadd_rn(x.w, __fsub_rn(q.w, x.w));
        *(float4*)(out + (size_t)(row0 + m) * D + c * 4) = r;
    }
}

// ---------------------------------------------------------------------------
// Finalize: vq_loss = 1.25 * mean(dist) written as last output element.
// ---------------------------------------------------------------------------
__global__ void vq_finish(float* __restrict__ out, int total_elems) {
    out[total_elems] = (float)(1.25 * g_loss_accum / (double)total_elems);
}

extern "C" void kernel_launch(void* const* d_in, const int* in_sizes, int n_in,
                              void* d_out, int out_size) {
    const float* X = (const float*)d_in[0];   // latents  [8192, 2048] fp32
    const float* E = (const float*)d_in[1];   // embedding [1024, 256] fp32
    float* out = (float*)d_out;
    int M = in_sizes[0] / D;                  // 65536 flattened rows

    vq_prep<<<KC, 64>>>(E);
    vq_main<<<M / BM, 256>>>(X, E, out);
    vq_finish<<<1, 1>>>(out, out_size - 1);
}

// round 5
// speedup vs baseline: 1.1013x; 1.1013x over previous
#include <cuda_runtime.h>
#include <cstdint>

#define D   256
#define KC  1024
#define M_ROWS 65536

// ---- filter smem layout ----
#define FS_EN  0          // 128 floats
#define FS_A   1024       // 128 rows x 260 floats = 133120 B
#define FS_B   134144     // 2 bufs x 18432 B
#define FS_TOTAL 171008

#define B_TILE_FLOATS 4608   // 128 codes x 36
#define B_TILE_BYTES  18432
#define B_TILE_U16    1152   // 16B units

#define WINF 1.5e-4f

__device__ double g_loss_accum;
__device__ __align__(16) float g_enorm[KC];
__device__ __align__(16) float g_xn[M_ROWS];
__device__ __align__(16) int4  g_cand[M_ROWS];
// 64 tiles: [nc(8)][kc(8)] x [code(128)][36 floats] (tf32 plane-0 of E)
__device__ __align__(16) float g_Bp[64 * B_TILE_FLOATS];

__device__ __forceinline__ uint32_t smem_u32(const void* p) {
    uint32_t a;
    asm("{ .reg .u64 t; cvta.to.shared.u64 t, %1; cvt.u32.u64 %0, t; }" : "=r"(a) : "l"(p));
    return a;
}
__device__ __forceinline__ uint32_t f2tf32(float x) {
    uint32_t r; asm("cvt.rna.tf32.f32 %0, %1;" : "=r"(r) : "f"(x)); return r;
}
__device__ __forceinline__ void mma_tf32(float* c, const uint32_t* a, uint32_t b0, uint32_t b1) {
    asm volatile("mma.sync.aligned.m16n8k8.row.col.f32.tf32.tf32.f32 "
                 "{%0,%1,%2,%3}, {%4,%5,%6,%7}, {%8,%9}, {%0,%1,%2,%3};"
                 : "+f"(c[0]), "+f"(c[1]), "+f"(c[2]), "+f"(c[3])
                 : "r"(a[0]), "r"(a[1]), "r"(a[2]), "r"(a[3]), "r"(b0), "r"(b1));
}
#define CP_COMMIT() asm volatile("cp.async.commit_group;" ::: "memory")
#define CP_WAIT1()  asm volatile("cp.async.wait_group 1;" ::: "memory")
#define CP_WAIT0()  asm volatile("cp.async.wait_group 0;" ::: "memory")

__device__ __forceinline__ void issue_tile(uint32_t dst, const float* src, int tid) {
    #pragma unroll
    for (int j = 0; j < 5; j++) {
        int o = tid + j * 256;
        if (o < B_TILE_U16)
            asm volatile("cp.async.cg.shared.global [%0], [%1], 16;"
                         :: "r"(dst + o * 16), "l"(src + o * 4));
    }
}

// value-then-lowest-index comparator (reference tie-break)
__device__ __forceinline__ bool bt(float va, int ia, float vb, int ib) {
    return va < vb || (va == vb && ia < ib);
}

// ---------------------------------------------------------------------------
// Prep: e-norms (R2-verbatim reduction), tf32 plane-0 E tile images, zero loss.
// ---------------------------------------------------------------------------
__global__ void vq_prep(const float* __restrict__ E) {
    int code = blockIdx.x;
    int t = threadIdx.x;          // 64 threads, 4 elems each
    const float4* row = (const float4*)(E + (size_t)code * D);
    float4 v = row[t];
    float s = v.x * v.x + v.y * v.y + v.z * v.z + v.w * v.w;
    #pragma unroll
    for (int o = 16; o > 0; o >>= 1) s += __shfl_xor_sync(0xFFFFFFFFu, s, o);
    __shared__ float ws[2];
    if ((t & 31) == 0) ws[t >> 5] = s;
    __syncthreads();
    if (t == 0) {
        g_enorm[code] = ws[0] + ws[1];
        if (code == 0) g_loss_accum = 0.0;
    }

    // tf32 plane-0 into tile images (filter operand)
    int nc = code >> 7, c = code & 127;
    float f[4] = {v.x, v.y, v.z, v.w};
    #pragma unroll
    for (int e = 0; e < 4; e++) {
        int k  = t * 4 + e;
        int kc = k >> 5, kk = k & 31;
        *(uint32_t*)&g_Bp[(size_t)(nc * 8 + kc) * B_TILE_FLOATS + (size_t)c * 36 + kk]
            = f2tf32(f[e]);
    }
}

// ---------------------------------------------------------------------------
// xnorm: R2's per-row ||x||^2 code, verbatim structure -> global array.
// ---------------------------------------------------------------------------
__global__ void vq_xnorm(const float* __restrict__ X) {
    int tid = threadIdx.x;
    int row0 = blockIdx.x * 128;
    int r = tid >> 1, h = tid & 1;
    const float4* xr = (const float4*)(X + (size_t)(row0 + r) * D + h * 128);
    float s = 0.f;
    #pragma unroll
    for (int j = 0; j < 32; j++) {
        float4 v = xr[j];
        s += v.x * v.x + v.y * v.y + v.z * v.z + v.w * v.w;
    }
    s += __shfl_xor_sync(0xFFFFFFFFu, s, 1);
    if (h == 0) g_xn[row0 + r] = s;
}

// ---------------------------------------------------------------------------
// Filter: tf32 single-pass warp-MMA, top-3 candidates per row + fallback flag.
// 512 CTAs x 256 threads, BM=128, all 1024 codes/CTA.
// ---------------------------------------------------------------------------
__global__ void __launch_bounds__(256, 1)
vq_filter(const float* __restrict__ X) {
    extern __shared__ char sm[];
    const uint32_t smb = smem_u32(sm);
    const int tid  = threadIdx.x;
    const int lane = tid & 31;
    const int warp = tid >> 5;
    const int row0 = blockIdx.x * 128;

    float* As   = (float*)(sm + FS_A);
    float* s_en = (float*)(sm + FS_EN);

    // A tile into smem (row stride 260)
    for (int i = tid; i < 128 * 64; i += 256) {
        int r = i >> 6, c4 = i & 63;
        float4 v = *(const float4*)(X + (size_t)(row0 + r) * D + c4 * 4);
        *(float4*)(As + r * 260 + c4 * 4) = v;
    }
    issue_tile(smb + FS_B, g_Bp, tid);
    CP_COMMIT();
    __syncthreads();

    const int rA = warp * 16 + (lane >> 2);
    const float* pA0 = As + rA * 260 + (lane & 3);
    const float* pA1 = pA0 + 8 * 260;

    // top-3 per row-slot (slot0 = rA, slot1 = rA+8)
    float v1[2] = {3e38f, 3e38f}, v2[2] = {3e38f, 3e38f}, v3[2] = {3e38f, 3e38f};
    int   i1[2] = {0, 0},         i2[2] = {0, 0},         i3[2] = {0, 0};

    #define INS3(slot, sv, sidx) do { \
        float _s = (sv); int _i = (sidx); \
        if (_s < v3[slot]) { \
            if (_s < v2[slot]) { \
                v3[slot] = v2[slot]; i3[slot] = i2[slot]; \
                if (_s < v1[slot]) { v2[slot] = v1[slot]; i2[slot] = i1[slot]; \
                                     v1[slot] = _s; i1[slot] = _i; } \
                else               { v2[slot] = _s; i2[slot] = _i; } \
            } else { v3[slot] = _s; i3[slot] = _i; } \
        } } while (0)

    for (int nc = 0; nc < 8; nc++) {
        __syncthreads();
        if (tid < 128) s_en[tid] = g_enorm[nc * 128 + tid];

        float C[16][4];
        #pragma unroll
        for (int nt = 0; nt < 16; nt++)
            #pragma unroll
            for (int j = 0; j < 4; j++) C[nt][j] = 0.f;

        for (int kc = 0; kc < 8; kc++) {
            int tl = nc * 8 + kc;
            __syncthreads();
            if (tl < 63) {
                issue_tile(smb + FS_B + ((tl + 1) & 1) * B_TILE_BYTES,
                           g_Bp + (size_t)(tl + 1) * B_TILE_FLOATS, tid);
                CP_COMMIT();
                CP_WAIT1();
            } else {
                CP_WAIT0();
            }
            __syncthreads();

            const float* pB = (const float*)(sm + FS_B + (tl & 1) * B_TILE_BYTES)
                            + (lane >> 2) * 36 + (lane & 3);
            #pragma unroll
            for (int k8 = 0; k8 < 4; k8++) {
                int kg = kc * 32 + k8 * 8;
                uint32_t a[4];
                a[0] = f2tf32(pA0[kg]);
                a[1] = f2tf32(pA1[kg]);
                a[2] = f2tf32(pA0[kg + 4]);
                a[3] = f2tf32(pA1[kg + 4]);
                #pragma unroll
                for (int nt = 0; nt < 16; nt++) {
                    const float* pb = pB + nt * (8 * 36) + k8 * 8;
                    mma_tf32(C[nt], a, __float_as_uint(pb[0]), __float_as_uint(pb[4]));
                }
            }
        }

        // epilogue: approx score = en - 2*dot (xn-free ranking), insert top-3
        #pragma unroll
        for (int nt = 0; nt < 16; nt++) {
            int cl = nt * 8 + (lane & 3) * 2;
            int col0 = nc * 128 + cl;
            float en0 = s_en[cl], en1 = s_en[cl + 1];
            INS3(0, __fmaf_rn(-2.f, C[nt][0], en0), col0);
            INS3(0, __fmaf_rn(-2.f, C[nt][1], en1), col0 + 1);
            INS3(1, __fmaf_rn(-2.f, C[nt][2], en0), col0);
            INS3(1, __fmaf_rn(-2.f, C[nt][3], en1), col0 + 1);
        }
    }

    // quad merge (lanes sharing rows): merge sorted triples, lowest-index ties
    #pragma unroll
    for (int o = 1; o < 4; o <<= 1) {
        #pragma unroll
        for (int sl = 0; sl < 2; sl++) {
            float tv[3]; int ti[3];
            tv[0] = __shfl_xor_sync(0xFFFFFFFFu, v1[sl], o);
            ti[0] = __shfl_xor_sync(0xFFFFFFFFu, i1[sl], o);
            tv[1] = __shfl_xor_sync(0xFFFFFFFFu, v2[sl], o);
            ti[1] = __shfl_xor_sync(0xFFFFFFFFu, i2[sl], o);
            tv[2] = __shfl_xor_sync(0xFFFFFFFFu, v3[sl], o);
            ti[2] = __shfl_xor_sync(0xFFFFFFFFu, i3[sl], o);
            float mv[3] = {v1[sl], v2[sl], v3[sl]};
            int   mi[3] = {i1[sl], i2[sl], i3[sl]};
            float rv[3]; int ri[3];
            int a = 0, b = 0;
            #pragma unroll
            for (int k = 0; k < 3; k++) {
                bool ta = (b >= 3) || (a < 3 && bt(mv[a], mi[a], tv[b], ti[b]));
                rv[k] = ta ? mv[a] : tv[b];
                ri[k] = ta ? mi[a] : ti[b];
                if (ta) a++; else b++;
            }
            v1[sl] = rv[0]; i1[sl] = ri[0];
            v2[sl] = rv[1]; i2[sl] = ri[1];
            v3[sl] = rv[2]; i3[sl] = ri[2];
        }
    }

    if ((lane & 3) == 0) {
        int f0 = (v3[0] < v1[0] + WINF) ? 1 : 0;
        int f1 = (v3[1] < v1[1] + WINF) ? 1 : 0;
        g_cand[row0 + rA]     = make_int4(i1[0], i2[0], i3[0], f0);
        g_cand[row0 + rA + 8] = make_int4(i1[1], i2[1], i3[1], f1);
    }
}

// ---------------------------------------------------------------------------
// Refine: exact R2-order dots for candidates, snap, pick, loss, STE output.
// One warp per row; 8 warps / 256-thread block.
// ---------------------------------------------------------------------------
__device__ __forceinline__ float dot_chain(const float* sx, const float* e) {
    float d = 0.f;
    #pragma unroll 8
    for (int k = 0; k < 256; k++) d = __fmaf_rn(sx[k], __ldg(&e[k]), d);
    return d;
}

__global__ void __launch_bounds__(256, 4)
vq_refine(const float* __restrict__ X, const float* __restrict__ E,
          float* __restrict__ out) {
    __shared__ float sx[8][256];
    __shared__ float wloss[8];
    const int tid  = threadIdx.x;
    const int lane = tid & 31;
    const int warp = tid >> 5;
    const int row  = blockIdx.x * 8 + warp;

    const float4* xr = (const float4*)(X + (size_t)row * D);
    float4 va = xr[lane], vb = xr[lane + 32];
    ((float4*)sx[warp])[lane]      = va;
    ((float4*)sx[warp])[lane + 32] = vb;
    __syncwarp();

    const float xn = g_xn[row];
    const int4 cd = g_cand[row];

    float bv = 3e38f; int bn = 0;
    if (!cd.w) {
        if (lane < 3) {
            int c = (lane == 0) ? cd.x : (lane == 1) ? cd.y : cd.z;
            float d = dot_chain(sx[warp], E + (size_t)c * D);
            float t = __fadd_rn(xn, __ldg(&g_enorm[c]));
            bv = __fmaf_rn(-2.f, d, t);
            bn = c;
        }
    } else {
        // full scan: 4 interleaved chains per lane, indices ascending
        for (int c0 = lane; c0 < KC; c0 += 128) {
            const float* e0 = E + (size_t)(c0)       * D;
            const float* e1 = E + (size_t)(c0 + 32)  * D;
            const float* e2 = E + (size_t)(c0 + 64)  * D;
            const float* e3 = E + (size_t)(c0 + 96)  * D;
            float d0 = 0.f, d1 = 0.f, d2 = 0.f, d3 = 0.f;
            const float* x = sx[warp];
            #pragma unroll 8
            for (int k = 0; k < 256; k++) {
                float xv = x[k];
                d0 = __fmaf_rn(xv, __ldg(&e0[k]), d0);
                d1 = __fmaf_rn(xv, __ldg(&e1[k]), d1);
                d2 = __fmaf_rn(xv, __ldg(&e2[k]), d2);
                d3 = __fmaf_rn(xv, __ldg(&e3[k]), d3);
            }
            float s;
            s = __fmaf_rn(-2.f, d0, __fadd_rn(xn, __ldg(&g_enorm[c0])));
            if (bt(s, c0, bv, bn)) { bv = s; bn = c0; }
            s = __fmaf_rn(-2.f, d1, __fadd_rn(xn, __ldg(&g_enorm[c0 + 32])));
            if (bt(s, c0 + 32, bv, bn)) { bv = s; bn = c0 + 32; }
            s = __fmaf_rn(-2.f, d2, __fadd_rn(xn, __ldg(&g_enorm[c0 + 64])));
            if (bt(s, c0 + 64, bv, bn)) { bv = s; bn = c0 + 64; }
            s = __fmaf_rn(-2.f, d3, __fadd_rn(xn, __ldg(&g_enorm[c0 + 96])));
            if (bt(s, c0 + 96, bv, bn)) { bv = s; bn = c0 + 96; }
        }
    }

    // warp argmin, lowest-index ties
    #pragma unroll
    for (int o = 16; o > 0; o >>= 1) {
        float ov = __shfl_xor_sync(0xFFFFFFFFu, bv, o);
        int   on = __shfl_xor_sync(0xFFFFFFFFu, bn, o);
        if (bt(ov, on, bv, bn)) { bv = ov; bn = on; }
    }

    if (lane == 0) wloss[warp] = bv;

    // STE output: out = fl(x + fl(q - x))
    const float4* er = (const float4*)(E + (size_t)bn * D);
    float4 q = er[lane];
    float4 r;
    r.x = __fadd_rn(va.x, __fsub_rn(q.x, va.x));
    r.y = __fadd_rn(va.y, __fsub_rn(q.y, va.y));
    r.z = __fadd_rn(va.z, __fsub_rn(q.z, va.z));
    r.w = __fadd_rn(va.w, __fsub_rn(q.w, va.w));
    ((float4*)(out + (size_t)row * D))[lane] = r;
    q = er[lane + 32];
    r.x = __fadd_rn(vb.x, __fsub_rn(q.x, vb.x));
    r.y = __fadd_rn(vb.y, __fsub_rn(q.y, vb.y));
    r.z = __fadd_rn(vb.z, __fsub_rn(q.z, vb.z));
    r.w = __fadd_rn(vb.w, __fsub_rn(q.w, vb.w));
    ((float4*)(out + (size_t)row * D))[lane + 32] = r;

    __syncthreads();
    if (tid == 0) {
        float t = 0.f;
        #pragma unroll
        for (int w = 0; w < 8; w++) t += wloss[w];
        atomicAdd(&g_loss_accum, (double)t);
    }
}

__global__ void vq_finish(float* __restrict__ out, int total_elems) {
    out[total_elems] = (float)(1.25 * g_loss_accum / (double)total_elems);
}

extern "C" void kernel_launch(void* const* d_in, const int* in_sizes, int n_in,
                              void* d_out, int out_size) {
    const float* X = (const float*)d_in[0];   // latents  [8192, 2048] fp32
    const float* E = (const float*)d_in[1];   // embedding [1024, 256] fp32
    float* out = (float*)d_out;
    int M = in_sizes[0] / D;                  // 65536 rows

    cudaFuncSetAttribute(vq_filter, cudaFuncAttributeMaxDynamicSharedMemorySize, FS_TOTAL);
    vq_prep<<<KC, 64>>>(E);
    vq_xnorm<<<M / 128, 256>>>(X);
    vq_filter<<<M / 128, 256, FS_TOTAL>>>(X);
    vq_refine<<<M / 8, 256>>>(X, E, out);
    vq_finish<<<1, 1>>>(out, out_size - 1);
}